// round 9
// baseline (speedup 1.0000x reference)
#include <cuda_runtime.h>
#include <cstdint>

// Problem: logits = X[8192,1024] @ W[50257,1024]^T  (fp32), plus
// loss = mean_n( logsumexp(logits[n,:]) - logits[n, target[n]] )
// out[0 .. M*N) = logits row-major, out[out_size-1] = loss.

#define BM 128
#define BN 128
#define BK 32
#define AS_STRIDE 36              // BK + 4 pad -> conflict-free frag loads & float4 STS
#define TILE_FLOATS (BM * AS_STRIDE)   // 4608 floats per buffer per matrix
#define SMEM_BYTES (4 * TILE_FLOATS * 4)  // 2 bufs x (A + B) = 73728 B

__device__ float g_row_nll[8192];

// ---------------------------------------------------------------------------
// helpers
// ---------------------------------------------------------------------------

__device__ __forceinline__ float to_tf32(float x) {
    // round-to-nearest tf32 (truncation would bias the K=1024 dot by ~1e-3)
    uint32_t u;
    asm("cvt.rna.tf32.f32 %0, %1;" : "=r"(u) : "f"(x));
    return __uint_as_float(u);
}

__device__ __forceinline__ void mma_tf32(float* d, const float* a, const float* b) {
    asm volatile(
        "mma.sync.aligned.m16n8k8.row.col.f32.tf32.tf32.f32 "
        "{%0,%1,%2,%3}, {%4,%5,%6,%7}, {%8,%9}, {%0,%1,%2,%3};\n"
        : "+f"(d[0]), "+f"(d[1]), "+f"(d[2]), "+f"(d[3])
        : "r"(__float_as_uint(a[0])), "r"(__float_as_uint(a[1])),
          "r"(__float_as_uint(a[2])), "r"(__float_as_uint(a[3])),
          "r"(__float_as_uint(b[0])), "r"(__float_as_uint(b[1])));
}

// fast e^x for x <= 0, on the FMA pipe (avoids the ~2.9 ms MUFU bottleneck
// that 411M expf() calls would cost).  2^f poly on f in [-0.5, 0.5]:
// max rel err ~2e-6, far under the 1e-3 budget.
__device__ __forceinline__ float fexp(float x) {
    float y = fmaxf(x * 1.4426950408889634f, -126.0f);
    float r = rintf(y);
    float f = y - r;
    float p = 1.3333558146428443e-3f;
    p = fmaf(p, f, 9.618129107628477e-3f);
    p = fmaf(p, f, 5.550410866482158e-2f);
    p = fmaf(p, f, 2.402265069591007e-1f);
    p = fmaf(p, f, 6.931471805599453e-1f);
    p = fmaf(p, f, 1.0f);
    return p * __int_as_float(((int)r + 127) << 23);
}

// ---------------------------------------------------------------------------
// GEMM: C[m,n] = sum_k A[m,k] * B[n,k]   (A row-major, B row-major = "col" B)
// 128x128x32 tile, 256 threads (8 warps, 2x4), warp tile 64x32, m16n8k8 tf32.
// Double-buffered smem via register staging (cvt.rna applied on the g->s path).
// ---------------------------------------------------------------------------

__device__ __forceinline__ void load_g2r(const float* __restrict__ A,
                                         const float* __restrict__ B,
                                         int m0, int n0, int N, int K, int kk,
                                         int tid, float4* ra, float4* rb) {
#pragma unroll
    for (int i = 0; i < 4; i++) {
        int id = tid + i * 256;
        int r = id >> 3, c4 = id & 7;
        ra[i] = *reinterpret_cast<const float4*>(A + (size_t)(m0 + r) * K + kk + c4 * 4);
        if (n0 + r < N)
            rb[i] = *reinterpret_cast<const float4*>(B + (size_t)(n0 + r) * K + kk + c4 * 4);
        else
            rb[i] = make_float4(0.f, 0.f, 0.f, 0.f);
    }
}

__device__ __forceinline__ void store_r2s(float* As, float* Bs, int tid,
                                          const float4* ra, const float4* rb) {
#pragma unroll
    for (int i = 0; i < 4; i++) {
        int id = tid + i * 256;
        int r = id >> 3, c4 = id & 7;
        float4 a = ra[i], b = rb[i];
        float4 ca = make_float4(to_tf32(a.x), to_tf32(a.y), to_tf32(a.z), to_tf32(a.w));
        float4 cb = make_float4(to_tf32(b.x), to_tf32(b.y), to_tf32(b.z), to_tf32(b.w));
        *reinterpret_cast<float4*>(As + r * AS_STRIDE + c4 * 4) = ca;
        *reinterpret_cast<float4*>(Bs + r * AS_STRIDE + c4 * 4) = cb;
    }
}

__global__ __launch_bounds__(256, 1)
void gemm_tf32_kernel(const float* __restrict__ A, const float* __restrict__ B,
                      float* __restrict__ C, int M, int N, int K) {
    extern __shared__ float smem[];
    float* As = smem;                       // 2 buffers
    float* Bs = smem + 2 * TILE_FLOATS;     // 2 buffers

    const int tid = threadIdx.x;
    const int m0 = blockIdx.y * BM;
    const int n0 = blockIdx.x * BN;

    const int lane = tid & 31;
    const int g = lane >> 2;   // 0..7
    const int tg = lane & 3;   // 0..3
    const int wid = tid >> 5;
    const int wm = (wid >> 2) * 64;  // warp row base in tile
    const int wn = (wid & 3) * 32;   // warp col base in tile

    float acc[4][4][4];
#pragma unroll
    for (int mt = 0; mt < 4; mt++)
#pragma unroll
        for (int nt = 0; nt < 4; nt++)
#pragma unroll
            for (int i = 0; i < 4; i++) acc[mt][nt][i] = 0.f;

    const int tiles = K / BK;

    {
        float4 ra[4], rb[4];
        load_g2r(A, B, m0, n0, N, K, 0, tid, ra, rb);
        store_r2s(As, Bs, tid, ra, rb);
    }
    __syncthreads();

    for (int t = 0; t < tiles; t++) {
        float4 ra[4], rb[4];
        const bool pf = (t + 1 < tiles);
        if (pf) load_g2r(A, B, m0, n0, N, K, (t + 1) * BK, tid, ra, rb);

        const float* Ac = As + (t & 1) * TILE_FLOATS;
        const float* Bc = Bs + (t & 1) * TILE_FLOATS;

#pragma unroll
        for (int ks = 0; ks < 4; ks++) {
            const int k = ks * 8;
            float a[4][4], b[4][2];
#pragma unroll
            for (int mt = 0; mt < 4; mt++) {
                const float* p = Ac + (wm + mt * 16 + g) * AS_STRIDE + k + tg;
                a[mt][0] = p[0];
                a[mt][1] = p[8 * AS_STRIDE];
                a[mt][2] = p[4];
                a[mt][3] = p[8 * AS_STRIDE + 4];
            }
#pragma unroll
            for (int nt = 0; nt < 4; nt++) {
                const float* p = Bc + (wn + nt * 8 + g) * AS_STRIDE + k + tg;
                b[nt][0] = p[0];
                b[nt][1] = p[4];
            }
#pragma unroll
            for (int mt = 0; mt < 4; mt++)
#pragma unroll
                for (int nt = 0; nt < 4; nt++)
                    mma_tf32(acc[mt][nt], a[mt], b[nt]);
        }

        if (pf) {
            store_r2s(As + ((t + 1) & 1) * TILE_FLOATS,
                      Bs + ((t + 1) & 1) * TILE_FLOATS, tid, ra, rb);
        }
        __syncthreads();
    }

    // epilogue (N=50257 is odd -> scalar stores to keep alignment legal)
#pragma unroll
    for (int mt = 0; mt < 4; mt++) {
        int r = m0 + wm + mt * 16 + g;
        size_t b0 = (size_t)r * N;
        size_t b1 = (size_t)(r + 8) * N;
#pragma unroll
        for (int nt = 0; nt < 4; nt++) {
            int c = n0 + wn + nt * 8 + 2 * tg;
            const float* d = acc[mt][nt];
            if (c < N)     { C[b0 + c] = d[0];     C[b1 + c] = d[2]; }
            if (c + 1 < N) { C[b0 + c + 1] = d[1]; C[b1 + c + 1] = d[3]; }
        }
    }
}

// ---------------------------------------------------------------------------
// Per-row logsumexp + NLL. Two passes (max, then sum-exp) so the exp chain
// pipelines; second pass hits L2 (row = 200 KB, well within working set).
// Targets read as int32 (the harness materializes int64 inputs as int32).
// ---------------------------------------------------------------------------

__global__ __launch_bounds__(256)
void lse_nll_kernel(const float* __restrict__ logits,
                    const int* __restrict__ targets, int N) {
    __shared__ float red[8];
    __shared__ float row_max_sh;
    const int row = blockIdx.x;
    const int tid = threadIdx.x;
    const float* x = logits + (size_t)row * N;

    float mx = -3.4e38f;
    for (int j = tid; j < N; j += 256) mx = fmaxf(mx, x[j]);
#pragma unroll
    for (int o = 16; o; o >>= 1) mx = fmaxf(mx, __shfl_xor_sync(0xffffffffu, mx, o));
    if ((tid & 31) == 0) red[tid >> 5] = mx;
    __syncthreads();
    if (tid < 32) {
        float v = (tid < 8) ? red[tid] : -3.4e38f;
#pragma unroll
        for (int o = 4; o; o >>= 1) v = fmaxf(v, __shfl_xor_sync(0xffffffffu, v, o));
        if (tid == 0) row_max_sh = v;
    }
    __syncthreads();
    const float rmax = row_max_sh;

    float s = 0.f;
    for (int j = tid; j < N; j += 256) s += fexp(x[j] - rmax);
#pragma unroll
    for (int o = 16; o; o >>= 1) s += __shfl_xor_sync(0xffffffffu, s, o);
    if ((tid & 31) == 0) red[tid >> 5] = s;
    __syncthreads();
    if (tid == 0) {
        float tot = 0.f;
#pragma unroll
        for (int w = 0; w < 8; w++) tot += red[w];
        int t = targets[row];
        // defensive clamp: a bad index must never take the whole run down
        t = (t < 0) ? 0 : (t >= N ? N - 1 : t);
        g_row_nll[row] = rmax + logf(tot) - x[t];
    }
}

__global__ __launch_bounds__(256)
void mean_nll_kernel(float* __restrict__ loss_out, int M) {
    __shared__ float red[8];
    float s = 0.f;
    for (int j = threadIdx.x; j < M; j += 256) s += g_row_nll[j];
#pragma unroll
    for (int o = 16; o; o >>= 1) s += __shfl_xor_sync(0xffffffffu, s, o);
    if ((threadIdx.x & 31) == 0) red[threadIdx.x >> 5] = s;
    __syncthreads();
    if (threadIdx.x == 0) {
        float t = 0.f;
#pragma unroll
        for (int w = 0; w < 8; w++) t += red[w];
        loss_out[0] = t / (float)M;
    }
}

// ---------------------------------------------------------------------------
// launch — bind inputs BY ELEMENT COUNT (robust to metadata ordering):
//   targets: smallest buffer (M elements)
//   inputs : M * K
//   W      : largest buffer (N * K)
// ---------------------------------------------------------------------------

extern "C" void kernel_launch(void* const* d_in, const int* in_sizes, int n_in,
                              void* d_out, int out_size) {
    const int K = 1024;

    // find the three buffers by size
    int it = 0, ia = 0, iw = 0;
    for (int i = 1; i < n_in; i++) {
        if (in_sizes[i] < in_sizes[it]) it = i;
        if (in_sizes[i] > in_sizes[iw]) iw = i;
    }
    for (int i = 0; i < n_in; i++)
        if (i != it && i != iw) ia = i;

    const int* tgt = (const int*)d_in[it];     // targets [M] (int64 -> int32 in harness)
    const float* A = (const float*)d_in[ia];   // inputs  [M, K] fp32
    const float* W = (const float*)d_in[iw];   // W       [N, K] fp32
    float* out = (float*)d_out;

    const int M = in_sizes[ia] / K;   // 8192
    const int N = in_sizes[iw] / K;   // 50257

    cudaFuncSetAttribute((const void*)gemm_tf32_kernel,
                         cudaFuncAttributeMaxDynamicSharedMemorySize, SMEM_BYTES);

    dim3 grid((N + BN - 1) / BN, (M + BM - 1) / BM);
    gemm_tf32_kernel<<<grid, 256, SMEM_BYTES>>>(A, W, out, M, N, K);
    lse_nll_kernel<<<M, 256>>>(out, tgt, N);
    // loss goes in the final output slot (logits occupy the first M*N)
    mean_nll_kernel<<<1, 256>>>(out + (size_t)out_size - 1, M);
}

// round 10
// speedup vs baseline: 1.3135x; 1.3135x over previous
#include <cuda_runtime.h>
#include <cstdint>

// logits = X[8192,1024] @ W[50257,1024]^T (fp32 via tf32+rna), plus
// loss = mean_n( logsumexp(logits[n,:]) - logits[n, target[n]] )
// out[0 .. M*N) = logits row-major, out[out_size-1] = loss.

#define K_DIM 1024
#define M_DIM 8192
#define N_DIM 50257
#define NX_TILES 400                 // padded to 400 x-tiles (25 panels of 16)
#define NPAD (NX_TILES * 128)        // 51200 rows in padded W scratch
#define PW 16                        // panel width (x-tiles) for L2 rasterization

#define BM 128
#define BN 128
#define BK 32
#define AS_STRIDE 36                 // BK + 4 pad -> conflict-free frag loads
#define TILE_FLOATS (BM * AS_STRIDE) // 4608 floats / buffer / matrix
#define SMEM_BYTES (4 * TILE_FLOATS * 4)  // 2 bufs x (A+B) = 73728 B

// scratch: tf32-pre-rounded copies (W zero-padded); loss partials
__device__ float g_Ac[(size_t)M_DIM * K_DIM];        //  33.5 MB
__device__ float g_Wc[(size_t)NPAD * K_DIM];         // 209.7 MB
__device__ float g_row_nll[M_DIM];

// ---------------------------------------------------------------------------
// helpers
// ---------------------------------------------------------------------------

__device__ __forceinline__ float to_tf32(float x) {
    uint32_t u;
    asm("cvt.rna.tf32.f32 %0, %1;" : "=r"(u) : "f"(x));  // round-to-nearest tf32
    return __uint_as_float(u);
}

__device__ __forceinline__ void mma_tf32(float* d, const float* a, const float* b) {
    asm volatile(
        "mma.sync.aligned.m16n8k8.row.col.f32.tf32.tf32.f32 "
        "{%0,%1,%2,%3}, {%4,%5,%6,%7}, {%8,%9}, {%0,%1,%2,%3};\n"
        : "+f"(d[0]), "+f"(d[1]), "+f"(d[2]), "+f"(d[3])
        : "r"(__float_as_uint(a[0])), "r"(__float_as_uint(a[1])),
          "r"(__float_as_uint(a[2])), "r"(__float_as_uint(a[3])),
          "r"(__float_as_uint(b[0])), "r"(__float_as_uint(b[1])));
}

__device__ __forceinline__ void cp16(uint32_t dst_smem, const float* src) {
    asm volatile("cp.async.cg.shared.global [%0], [%1], 16;\n"
                 :: "r"(dst_smem), "l"(src));
}
__device__ __forceinline__ void cp_commit() {
    asm volatile("cp.async.commit_group;\n" ::: "memory");
}
template <int N_>
__device__ __forceinline__ void cp_wait() {
    asm volatile("cp.async.wait_group %0;\n" :: "n"(N_) : "memory");
}

// fast e^x for x <= 0 on the FMA pipe (411M MUFU EX2 would cost ~2.9 ms).
// max rel err ~2e-6.
__device__ __forceinline__ float fexp(float x) {
    float y = fmaxf(x * 1.4426950408889634f, -126.0f);
    float r = rintf(y);
    float f = y - r;
    float p = 1.3333558146428443e-3f;
    p = fmaf(p, f, 9.618129107628477e-3f);
    p = fmaf(p, f, 5.550410866482158e-2f);
    p = fmaf(p, f, 2.402265069591007e-1f);
    p = fmaf(p, f, 6.931471805599453e-1f);
    p = fmaf(p, f, 1.0f);
    return p * __int_as_float(((int)r + 127) << 23);
}

// ---------------------------------------------------------------------------
// pre-convert: apply tf32 rounding once, zero-pad W rows [N, NPAD)
// ---------------------------------------------------------------------------

__global__ __launch_bounds__(256)
void cvt_A_kernel(const float4* __restrict__ A) {
    const int n4 = M_DIM * K_DIM / 4;
    float4* dst = reinterpret_cast<float4*>(g_Ac);
    int stride = gridDim.x * blockDim.x;
    for (int i = blockIdx.x * blockDim.x + threadIdx.x; i < n4; i += stride) {
        float4 v = A[i];
        dst[i] = make_float4(to_tf32(v.x), to_tf32(v.y), to_tf32(v.z), to_tf32(v.w));
    }
}

__global__ __launch_bounds__(256)
void cvt_W_kernel(const float4* __restrict__ W) {
    const int n4_real  = N_DIM * (K_DIM / 4);   // 12,865,792
    const int n4_total = NPAD  * (K_DIM / 4);   // 13,107,200
    float4* dst = reinterpret_cast<float4*>(g_Wc);
    int stride = gridDim.x * blockDim.x;
    for (int i = blockIdx.x * blockDim.x + threadIdx.x; i < n4_total; i += stride) {
        if (i < n4_real) {
            float4 v = W[i];
            dst[i] = make_float4(to_tf32(v.x), to_tf32(v.y), to_tf32(v.z), to_tf32(v.w));
        } else {
            dst[i] = make_float4(0.f, 0.f, 0.f, 0.f);
        }
    }
}

// ---------------------------------------------------------------------------
// GEMM: C[m,n] = sum_k Ac[m,k] * Wc[n,k].  128x128x32 tile, 8 warps (2x4),
// warp tile 64x32, m16n8k8 tf32. cp.async 2-stage pipeline, 2 CTAs/SM.
// Grid raster: panels of PW x-tiles over all 64 y-tiles -> A stays in L2,
// W streams once.
// ---------------------------------------------------------------------------

__device__ __forceinline__ void issue_tile(uint32_t sA, uint32_t sB,
                                           const float* __restrict__ Abase,
                                           const float* __restrict__ Bbase,
                                           int kk, int tid) {
#pragma unroll
    for (int i = 0; i < 4; i++) {
        int id = tid + i * 256;
        int r = id >> 3, c4 = id & 7;
        uint32_t so = (uint32_t)(r * AS_STRIDE + c4 * 4) * 4u;
        cp16(sA + so, Abase + (size_t)r * K_DIM + kk + c4 * 4);
        cp16(sB + so, Bbase + (size_t)r * K_DIM + kk + c4 * 4);
    }
}

__global__ __launch_bounds__(256, 2)
void gemm_tf32_kernel(float* __restrict__ C) {
    extern __shared__ float smem[];
    const uint32_t sbase = (uint32_t)__cvta_generic_to_shared(smem);
    const uint32_t sA0 = sbase;                              // A buf0
    const uint32_t sB0 = sbase + 2u * TILE_FLOATS * 4u;      // B buf0
    const uint32_t bufstride = TILE_FLOATS * 4u;

    const int tid = threadIdx.x;

    // panel rasterization: bid -> (x, y)
    const int bid = blockIdx.x;
    const int panel = bid / (64 * PW);
    const int rem = bid % (64 * PW);
    const int y = rem & 63;
    const int x = panel * PW + (rem >> 6);

    const int m0 = y * BM;
    const int n0 = x * BN;

    const float* Abase = g_Ac + (size_t)m0 * K_DIM;
    const float* Bbase = g_Wc + (size_t)n0 * K_DIM;

    const int lane = tid & 31;
    const int g = lane >> 2;     // 0..7
    const int tg = lane & 3;     // 0..3
    const int wid = tid >> 5;
    const int wm = (wid >> 2) * 64;
    const int wn = (wid & 3) * 32;

    float acc[4][4][4];
#pragma unroll
    for (int mt = 0; mt < 4; mt++)
#pragma unroll
        for (int nt = 0; nt < 4; nt++)
#pragma unroll
            for (int i = 0; i < 4; i++) acc[mt][nt][i] = 0.f;

    const int tiles = K_DIM / BK;   // 32

    // prologue: tiles 0 and 1 in flight
    issue_tile(sA0, sB0, Abase, Bbase, 0, tid);
    cp_commit();
    issue_tile(sA0 + bufstride, sB0 + bufstride, Abase, Bbase, BK, tid);
    cp_commit();
    cp_wait<1>();         // tile 0 complete
    __syncthreads();

    for (int t = 0; t < tiles; t++) {
        const int b = t & 1;
        const float* Ac = smem + b * TILE_FLOATS;
        const float* Bc = smem + (2 + b) * TILE_FLOATS;

#pragma unroll
        for (int ks = 0; ks < 4; ks++) {
            const int k = ks * 8;
            float a[4][4], bfr[4][2];
#pragma unroll
            for (int mt = 0; mt < 4; mt++) {
                const float* p = Ac + (wm + mt * 16 + g) * AS_STRIDE + k + tg;
                a[mt][0] = p[0];
                a[mt][1] = p[8 * AS_STRIDE];
                a[mt][2] = p[4];
                a[mt][3] = p[8 * AS_STRIDE + 4];
            }
#pragma unroll
            for (int nt = 0; nt < 4; nt++) {
                const float* p = Bc + (wn + nt * 8 + g) * AS_STRIDE + k + tg;
                bfr[nt][0] = p[0];
                bfr[nt][1] = p[4];
            }
#pragma unroll
            for (int mt = 0; mt < 4; mt++)
#pragma unroll
                for (int nt = 0; nt < 4; nt++)
                    mma_tf32(acc[mt][nt], a[mt], bfr[nt]);
        }

        if (t + 2 < tiles) {
            __syncthreads();   // everyone done reading buf b before refill
            issue_tile(sA0 + b * bufstride, sB0 + b * bufstride,
                       Abase, Bbase, (t + 2) * BK, tid);
            cp_commit();
            cp_wait<1>();      // tile t+1 complete
            __syncthreads();
        } else if (t + 1 < tiles) {
            cp_wait<0>();      // last pending tile complete
            __syncthreads();
        }
    }

    // epilogue (N odd -> scalar stores; guard pad columns)
#pragma unroll
    for (int mt = 0; mt < 4; mt++) {
        int r = m0 + wm + mt * 16 + g;
        size_t b0 = (size_t)r * N_DIM;
        size_t b1 = (size_t)(r + 8) * N_DIM;
#pragma unroll
        for (int nt = 0; nt < 4; nt++) {
            int c = n0 + wn + nt * 8 + 2 * tg;
            const float* d = acc[mt][nt];
            if (c < N_DIM)     { C[b0 + c] = d[0];     C[b1 + c] = d[2]; }
            if (c + 1 < N_DIM) { C[b0 + c + 1] = d[1]; C[b1 + c + 1] = d[3]; }
        }
    }
}

// ---------------------------------------------------------------------------
// Per-row logsumexp + NLL (two passes; second pass mostly L2),
// then mean over rows.
// ---------------------------------------------------------------------------

__global__ __launch_bounds__(256)
void lse_nll_kernel(const float* __restrict__ logits,
                    const int* __restrict__ targets, int N) {
    __shared__ float red[8];
    __shared__ float row_max_sh;
    const int row = blockIdx.x;
    const int tid = threadIdx.x;
    const float* x = logits + (size_t)row * N;

    float mx = -3.4e38f;
    for (int j = tid; j < N; j += 256) mx = fmaxf(mx, x[j]);
#pragma unroll
    for (int o = 16; o; o >>= 1) mx = fmaxf(mx, __shfl_xor_sync(0xffffffffu, mx, o));
    if ((tid & 31) == 0) red[tid >> 5] = mx;
    __syncthreads();
    if (tid < 32) {
        float v = (tid < 8) ? red[tid] : -3.4e38f;
#pragma unroll
        for (int o = 4; o; o >>= 1) v = fmaxf(v, __shfl_xor_sync(0xffffffffu, v, o));
        if (tid == 0) row_max_sh = v;
    }
    __syncthreads();
    const float rmax = row_max_sh;

    float s = 0.f;
    for (int j = tid; j < N; j += 256) s += fexp(x[j] - rmax);
#pragma unroll
    for (int o = 16; o; o >>= 1) s += __shfl_xor_sync(0xffffffffu, s, o);
    if ((tid & 31) == 0) red[tid >> 5] = s;
    __syncthreads();
    if (tid == 0) {
        float tot = 0.f;
#pragma unroll
        for (int w = 0; w < 8; w++) tot += red[w];
        int t = targets[row];
        t = (t < 0) ? 0 : (t >= N ? N - 1 : t);
        g_row_nll[row] = rmax + logf(tot) - x[t];
    }
}

__global__ __launch_bounds__(256)
void mean_nll_kernel(float* __restrict__ loss_out, int M) {
    __shared__ float red[8];
    float s = 0.f;
    for (int j = threadIdx.x; j < M; j += 256) s += g_row_nll[j];
#pragma unroll
    for (int o = 16; o; o >>= 1) s += __shfl_xor_sync(0xffffffffu, s, o);
    if ((threadIdx.x & 31) == 0) red[threadIdx.x >> 5] = s;
    __syncthreads();
    if (threadIdx.x == 0) {
        float t = 0.f;
#pragma unroll
        for (int w = 0; w < 8; w++) t += red[w];
        loss_out[0] = t / (float)M;
    }
}

// ---------------------------------------------------------------------------
// launch — bind inputs BY ELEMENT COUNT (robust to metadata ordering)
// ---------------------------------------------------------------------------

extern "C" void kernel_launch(void* const* d_in, const int* in_sizes, int n_in,
                              void* d_out, int out_size) {
    int it = 0, ia = 0, iw = 0;
    for (int i = 1; i < n_in; i++) {
        if (in_sizes[i] < in_sizes[it]) it = i;
        if (in_sizes[i] > in_sizes[iw]) iw = i;
    }
    for (int i = 0; i < n_in; i++)
        if (i != it && i != iw) ia = i;

    const int* tgt = (const int*)d_in[it];     // targets [M] (int64 lowered to int32)
    const float* A = (const float*)d_in[ia];   // inputs  [M, K] fp32
    const float* W = (const float*)d_in[iw];   // W       [N, K] fp32
    float* out = (float*)d_out;

    const int M = in_sizes[ia] / K_DIM;   // 8192
    const int N = in_sizes[iw] / K_DIM;   // 50257

    cudaFuncSetAttribute((const void*)gemm_tf32_kernel,
                         cudaFuncAttributeMaxDynamicSharedMemorySize, SMEM_BYTES);

    cvt_A_kernel<<<2048, 256>>>(reinterpret_cast<const float4*>(A));
    cvt_W_kernel<<<8192, 256>>>(reinterpret_cast<const float4*>(W));

    gemm_tf32_kernel<<<NX_TILES * 64, 256, SMEM_BYTES>>>(out);

    lse_nll_kernel<<<M, 256>>>(out, tgt, N);
    mean_nll_kernel<<<1, 256>>>(out + (size_t)out_size - 1, M);
}

// round 11
// speedup vs baseline: 1.5160x; 1.1541x over previous
#include <cuda_runtime.h>
#include <cstdint>
#include <cfloat>

// logits = X[8192,1024] @ W[50257,1024]^T (fp32 via tf32+rna), plus
// loss = mean_n( logsumexp(logits[n,:]) - logits[n, target[n]] )
// out[0 .. M*N) = logits row-major, out[out_size-1] = loss.

#define K_DIM 1024
#define M_DIM 8192
#define N_DIM 50257
#define NX_TILES 400                 // padded x-tiles in W scratch (25 panels of 16)
#define NX_VALID 393                 // ceil(50257/128): tiles that produce output
#define NPAD (NX_TILES * 128)        // 51200 rows in padded W scratch
#define PW 16                        // panel width (x-tiles) for L2 rasterization

#define BM 128
#define BN 128
#define BK 32
#define AS_STRIDE 40                 // BK + 8 pad -> conflict-free float2 frag loads
#define TILE_FLOATS (BM * AS_STRIDE) // 5120 floats / buffer / matrix
#define SMEM_BYTES (4 * TILE_FLOATS * 4)  // 2 bufs x (A+B) = 81920 B

// scratch: tf32-pre-rounded, k-permuted copies (W zero-padded); per-tile row max
__device__ float g_Ac[(size_t)M_DIM * K_DIM];        //  33.5 MB
__device__ float g_Wc[(size_t)NPAD * K_DIM];         // 209.7 MB
__device__ float g_tmax[(size_t)M_DIM * NX_TILES];   //  13.1 MB
__device__ float g_row_nll[M_DIM];

// ---------------------------------------------------------------------------
// helpers
// ---------------------------------------------------------------------------

__device__ __forceinline__ float to_tf32(float x) {
    uint32_t u;
    asm("cvt.rna.tf32.f32 %0, %1;" : "=r"(u) : "f"(x));  // round-to-nearest tf32
    return __uint_as_float(u);
}

__device__ __forceinline__ void mma_tf32(float* d, float a0, float a1, float a2,
                                         float a3, float b0, float b1) {
    asm volatile(
        "mma.sync.aligned.m16n8k8.row.col.f32.tf32.tf32.f32 "
        "{%0,%1,%2,%3}, {%4,%5,%6,%7}, {%8,%9}, {%0,%1,%2,%3};\n"
        : "+f"(d[0]), "+f"(d[1]), "+f"(d[2]), "+f"(d[3])
        : "r"(__float_as_uint(a0)), "r"(__float_as_uint(a1)),
          "r"(__float_as_uint(a2)), "r"(__float_as_uint(a3)),
          "r"(__float_as_uint(b0)), "r"(__float_as_uint(b1)));
}

__device__ __forceinline__ void cp16(uint32_t dst_smem, const float* src) {
    asm volatile("cp.async.cg.shared.global [%0], [%1], 16;\n"
                 :: "r"(dst_smem), "l"(src));
}
__device__ __forceinline__ void cp_commit() {
    asm volatile("cp.async.commit_group;\n" ::: "memory");
}
template <int N_>
__device__ __forceinline__ void cp_wait() {
    asm volatile("cp.async.wait_group %0;\n" :: "n"(N_) : "memory");
}

// fast e^x for x <= 0 on the FMA pipe (411M MUFU EX2 would cost ~2.9 ms).
__device__ __forceinline__ float fexp(float x) {
    float y = fmaxf(x * 1.4426950408889634f, -126.0f);
    float r = rintf(y);
    float f = y - r;
    float p = 1.3333558146428443e-3f;
    p = fmaf(p, f, 9.618129107628477e-3f);
    p = fmaf(p, f, 5.550410866482158e-2f);
    p = fmaf(p, f, 2.402265069591007e-1f);
    p = fmaf(p, f, 6.931471805599453e-1f);
    p = fmaf(p, f, 1.0f);
    return p * __int_as_float(((int)r + 127) << 23);
}

// ---------------------------------------------------------------------------
// pre-convert: tf32-round once AND permute k within each 8-group so the mma
// fragment pair (k, k+4) is contiguous: logical l -> phys (l&3)*2 + (l>>2).
// 8 consecutive logical floats (lo,hi) -> phys {lo.x,hi.x,lo.y,hi.y,
//                                               lo.z,hi.z,lo.w,hi.w}
// ---------------------------------------------------------------------------

__device__ __forceinline__ void perm_store(float4* dst, int i8, float4 lo, float4 hi) {
    dst[2 * i8]     = make_float4(to_tf32(lo.x), to_tf32(hi.x), to_tf32(lo.y), to_tf32(hi.y));
    dst[2 * i8 + 1] = make_float4(to_tf32(lo.z), to_tf32(hi.z), to_tf32(lo.w), to_tf32(hi.w));
}

__global__ __launch_bounds__(256)
void cvt_A_kernel(const float4* __restrict__ A) {
    const int n8 = M_DIM * K_DIM / 8;
    float4* dst = reinterpret_cast<float4*>(g_Ac);
    int stride = gridDim.x * blockDim.x;
    for (int i = blockIdx.x * blockDim.x + threadIdx.x; i < n8; i += stride)
        perm_store(dst, i, A[2 * i], A[2 * i + 1]);
}

__global__ __launch_bounds__(256)
void cvt_W_kernel(const float4* __restrict__ W) {
    const int n8_real  = N_DIM * (K_DIM / 8);
    const int n8_total = NPAD  * (K_DIM / 8);
    float4* dst = reinterpret_cast<float4*>(g_Wc);
    int stride = gridDim.x * blockDim.x;
    float4 z = make_float4(0.f, 0.f, 0.f, 0.f);
    for (int i = blockIdx.x * blockDim.x + threadIdx.x; i < n8_total; i += stride) {
        if (i < n8_real) perm_store(dst, i, W[2 * i], W[2 * i + 1]);
        else { dst[2 * i] = z; dst[2 * i + 1] = z; }
    }
}

// ---------------------------------------------------------------------------
// GEMM: C[m,n] = sum_k Ac[m,k] * Wc[n,k].  128x128x32 tile, 8 warps (2x4),
// warp tile 64x32, m16n8k8 tf32, float2 fragment loads, cp.async 2-stage,
// 2 CTAs/SM. Epilogue also emits per-tile row max into g_tmax.
// ---------------------------------------------------------------------------

__device__ __forceinline__ void issue_tile(uint32_t sA, uint32_t sB,
                                           const float* __restrict__ Abase,
                                           const float* __restrict__ Bbase,
                                           int kk, int tid) {
#pragma unroll
    for (int i = 0; i < 4; i++) {
        int id = tid + i * 256;
        int r = id >> 3, c4 = id & 7;
        uint32_t so = (uint32_t)(r * AS_STRIDE + c4 * 4) * 4u;
        cp16(sA + so, Abase + (size_t)r * K_DIM + kk + c4 * 4);
        cp16(sB + so, Bbase + (size_t)r * K_DIM + kk + c4 * 4);
    }
}

__global__ __launch_bounds__(256, 2)
void gemm_tf32_kernel(float* __restrict__ C) {
    extern __shared__ float smem[];
    const uint32_t sbase = (uint32_t)__cvta_generic_to_shared(smem);
    const uint32_t sA0 = sbase;
    const uint32_t sB0 = sbase + 2u * TILE_FLOATS * 4u;
    const uint32_t bufstride = TILE_FLOATS * 4u;

    const int tid = threadIdx.x;

    // panel rasterization: bid -> (x, y); y fastest so a wave shares A in L2
    const int bid = blockIdx.x;
    const int panel = bid / (64 * PW);
    const int rem = bid % (64 * PW);
    const int y = rem & 63;
    const int x = panel * PW + (rem >> 6);
    if (x >= NX_VALID) return;      // pad tiles produce no output

    const int m0 = y * BM;
    const int n0 = x * BN;

    const float* Abase = g_Ac + (size_t)m0 * K_DIM;
    const float* Bbase = g_Wc + (size_t)n0 * K_DIM;

    const int lane = tid & 31;
    const int g = lane >> 2;     // 0..7
    const int tg = lane & 3;     // 0..3
    const int wid = tid >> 5;
    const int wm = (wid >> 2) * 64;
    const int wn = (wid & 3) * 32;

    float acc[4][4][4];
#pragma unroll
    for (int mt = 0; mt < 4; mt++)
#pragma unroll
        for (int nt = 0; nt < 4; nt++)
#pragma unroll
            for (int i = 0; i < 4; i++) acc[mt][nt][i] = 0.f;

    const int tiles = K_DIM / BK;   // 32

    issue_tile(sA0, sB0, Abase, Bbase, 0, tid);
    cp_commit();
    issue_tile(sA0 + bufstride, sB0 + bufstride, Abase, Bbase, BK, tid);
    cp_commit();
    cp_wait<1>();
    __syncthreads();

    for (int t = 0; t < tiles; t++) {
        const int b = t & 1;
        const float* Ac = smem + b * TILE_FLOATS;
        const float* Bc = smem + (2 + b) * TILE_FLOATS;

#pragma unroll
        for (int ks = 0; ks < 4; ks++) {
            const int kc = ks * 8 + 2 * tg;   // permuted column of the k-pair
            float2 a0[4], a1[4], bf[4];
#pragma unroll
            for (int mt = 0; mt < 4; mt++) {
                const float2* pa = reinterpret_cast<const float2*>(
                    Ac + (wm + mt * 16 + g) * AS_STRIDE + kc);
                a0[mt] = pa[0];                         // row g      : (k, k+4)
                a1[mt] = pa[8 * AS_STRIDE / 2];         // row g+8    : (k, k+4)
            }
#pragma unroll
            for (int nt = 0; nt < 4; nt++)
                bf[nt] = *reinterpret_cast<const float2*>(
                    Bc + (wn + nt * 8 + g) * AS_STRIDE + kc);
#pragma unroll
            for (int mt = 0; mt < 4; mt++)
#pragma unroll
                for (int nt = 0; nt < 4; nt++)
                    mma_tf32(acc[mt][nt], a0[mt].x, a1[mt].x, a0[mt].y, a1[mt].y,
                             bf[nt].x, bf[nt].y);
        }

        if (t + 2 < tiles) {
            __syncthreads();
            issue_tile(sA0 + b * bufstride, sB0 + b * bufstride,
                       Abase, Bbase, (t + 2) * BK, tid);
            cp_commit();
            cp_wait<1>();
            __syncthreads();
        } else if (t + 1 < tiles) {
            cp_wait<0>();
            __syncthreads();
        }
    }

    // ---- store C (N odd -> scalar stores; guard pad columns) ----
#pragma unroll
    for (int mt = 0; mt < 4; mt++) {
        int r = m0 + wm + mt * 16 + g;
        size_t b0 = (size_t)r * N_DIM;
        size_t b1 = (size_t)(r + 8) * N_DIM;
#pragma unroll
        for (int nt = 0; nt < 4; nt++) {
            int c = n0 + wn + nt * 8 + 2 * tg;
            const float* d = acc[mt][nt];
            if (c < N_DIM)     { C[b0 + c] = d[0];     C[b1 + c] = d[2]; }
            if (c + 1 < N_DIM) { C[b0 + c + 1] = d[1]; C[b1 + c + 1] = d[3]; }
        }
    }

    // ---- per-tile row max -> g_tmax (fuses LSE pass 1 into the GEMM) ----
    __syncthreads();                 // done with smem tiles; reuse as reduce buf
    float* red = smem;               // [128 rows][4 col-slabs]
#pragma unroll
    for (int mt = 0; mt < 4; mt++) {
#pragma unroll
        for (int h = 0; h < 2; h++) {    // h=0: row g, h=1: row g+8
            float v = -FLT_MAX;
#pragma unroll
            for (int nt = 0; nt < 4; nt++) {
                int c = n0 + wn + nt * 8 + 2 * tg;
                const float* d = acc[mt][nt];
                if (c < N_DIM)     v = fmaxf(v, d[h ? 2 : 0]);
                if (c + 1 < N_DIM) v = fmaxf(v, d[h ? 3 : 1]);
            }
            v = fmaxf(v, __shfl_xor_sync(0xffffffffu, v, 1));
            v = fmaxf(v, __shfl_xor_sync(0xffffffffu, v, 2));
            if (tg == 0)
                red[(wm + mt * 16 + g + h * 8) * 4 + (wid & 3)] = v;
        }
    }
    __syncthreads();
    if (tid < 128) {
        float v = fmaxf(fmaxf(red[tid * 4 + 0], red[tid * 4 + 1]),
                        fmaxf(red[tid * 4 + 2], red[tid * 4 + 3]));
        g_tmax[(size_t)(m0 + tid) * NX_TILES + x] = v;
    }
}

// ---------------------------------------------------------------------------
// Per-row NLL: row max comes precomputed from g_tmax (tiny read), so the
// 1.65 GB logits array is streamed exactly ONCE for the sum-exp.
// ---------------------------------------------------------------------------

__global__ __launch_bounds__(256)
void lse_nll_kernel(const float* __restrict__ logits,
                    const int* __restrict__ targets) {
    __shared__ float red[8];
    __shared__ float row_max_sh;
    const int row = blockIdx.x;
    const int tid = threadIdx.x;
    const float* x = logits + (size_t)row * N_DIM;
    const float* tm = g_tmax + (size_t)row * NX_TILES;

    float mx = -FLT_MAX;
    for (int j = tid; j < NX_VALID; j += 256) mx = fmaxf(mx, tm[j]);
#pragma unroll
    for (int o = 16; o; o >>= 1) mx = fmaxf(mx, __shfl_xor_sync(0xffffffffu, mx, o));
    if ((tid & 31) == 0) red[tid >> 5] = mx;
    __syncthreads();
    if (tid < 32) {
        float v = (tid < 8) ? red[tid] : -FLT_MAX;
#pragma unroll
        for (int o = 4; o; o >>= 1) v = fmaxf(v, __shfl_xor_sync(0xffffffffu, v, o));
        if (tid == 0) row_max_sh = v;
    }
    __syncthreads();
    const float rmax = row_max_sh;

    float s = 0.f;
    for (int j = tid; j < N_DIM; j += 256) s += fexp(x[j] - rmax);
#pragma unroll
    for (int o = 16; o; o >>= 1) s += __shfl_xor_sync(0xffffffffu, s, o);
    if ((tid & 31) == 0) red[tid >> 5] = s;
    __syncthreads();
    if (tid == 0) {
        float tot = 0.f;
#pragma unroll
        for (int w = 0; w < 8; w++) tot += red[w];
        int t = targets[row];
        t = (t < 0) ? 0 : (t >= N_DIM ? N_DIM - 1 : t);
        g_row_nll[row] = rmax + logf(tot) - x[t];
    }
}

__global__ __launch_bounds__(256)
void mean_nll_kernel(float* __restrict__ loss_out, int M) {
    __shared__ float red[8];
    float s = 0.f;
    for (int j = threadIdx.x; j < M; j += 256) s += g_row_nll[j];
#pragma unroll
    for (int o = 16; o; o >>= 1) s += __shfl_xor_sync(0xffffffffu, s, o);
    if ((threadIdx.x & 31) == 0) red[threadIdx.x >> 5] = s;
    __syncthreads();
    if (threadIdx.x == 0) {
        float t = 0.f;
#pragma unroll
        for (int w = 0; w < 8; w++) t += red[w];
        loss_out[0] = t / (float)M;
    }
}

// ---------------------------------------------------------------------------
// launch — bind inputs BY ELEMENT COUNT (robust to metadata ordering)
// ---------------------------------------------------------------------------

extern "C" void kernel_launch(void* const* d_in, const int* in_sizes, int n_in,
                              void* d_out, int out_size) {
    int it = 0, ia = 0, iw = 0;
    for (int i = 1; i < n_in; i++) {
        if (in_sizes[i] < in_sizes[it]) it = i;
        if (in_sizes[i] > in_sizes[iw]) iw = i;
    }
    for (int i = 0; i < n_in; i++)
        if (i != it && i != iw) ia = i;

    const int* tgt = (const int*)d_in[it];     // targets [M] (int64 lowered to int32)
    const float* A = (const float*)d_in[ia];   // inputs  [M, K] fp32
    const float* W = (const float*)d_in[iw];   // W       [N, K] fp32
    float* out = (float*)d_out;

    const int M = in_sizes[ia] / K_DIM;   // 8192

    cudaFuncSetAttribute((const void*)gemm_tf32_kernel,
                         cudaFuncAttributeMaxDynamicSharedMemorySize, SMEM_BYTES);

    cvt_A_kernel<<<2048, 256>>>(reinterpret_cast<const float4*>(A));
    cvt_W_kernel<<<8192, 256>>>(reinterpret_cast<const float4*>(W));

    gemm_tf32_kernel<<<NX_TILES * 64, 256, SMEM_BYTES>>>(out);

    lse_nll_kernel<<<M, 256>>>(out, tgt);
    mean_nll_kernel<<<1, 256>>>(out + (size_t)out_size - 1, M);
}

// round 12
// speedup vs baseline: 1.5174x; 1.0010x over previous
#include <cuda_runtime.h>
#include <cstdint>
#include <cfloat>

// logits = X[8192,1024] @ W[50257,1024]^T (fp32 via tf32+rna), plus
// loss = mean_n( logsumexp(logits[n,:]) - logits[n, target[n]] )
// out[0 .. M*N) = logits row-major, out[out_size-1] = loss.

#define K_DIM 1024
#define M_DIM 8192
#define N_DIM 50257
#define NX_TILES 400                 // padded x-tiles in W scratch (25 panels of 16)
#define NX_VALID 393                 // ceil(50257/128): tiles that produce output
#define NPAD (NX_TILES * 128)        // 51200 rows in padded W scratch
#define PW 16                        // panel width (x-tiles) for L2 rasterization

#define BM 128
#define BN 128
#define BK 32
#define AS_STRIDE 40                 // BK + 8 pad -> conflict-free float2 frag loads
#define TILE_FLOATS (BM * AS_STRIDE) // 5120 floats / buffer / matrix
#define SMEM_BYTES (4 * TILE_FLOATS * 4)  // 2 bufs x (A+B) = 81920 B

// scratch: tf32-pre-rounded, k-permuted copies (W zero-padded); per-tile row max
__device__ float g_Ac[(size_t)M_DIM * K_DIM];        //  33.5 MB
__device__ float g_Wc[(size_t)NPAD * K_DIM];         // 209.7 MB
__device__ float g_tmax[(size_t)M_DIM * NX_TILES];   //  13.1 MB
__device__ float g_row_nll[M_DIM];

// ---------------------------------------------------------------------------
// helpers
// ---------------------------------------------------------------------------

__device__ __forceinline__ float to_tf32(float x) {
    uint32_t u;
    asm("cvt.rna.tf32.f32 %0, %1;" : "=r"(u) : "f"(x));  // round-to-nearest tf32
    return __uint_as_float(u);
}

__device__ __forceinline__ void mma_tf32(float* d, float a0, float a1, float a2,
                                         float a3, float b0, float b1) {
    asm volatile(
        "mma.sync.aligned.m16n8k8.row.col.f32.tf32.tf32.f32 "
        "{%0,%1,%2,%3}, {%4,%5,%6,%7}, {%8,%9}, {%0,%1,%2,%3};\n"
        : "+f"(d[0]), "+f"(d[1]), "+f"(d[2]), "+f"(d[3])
        : "r"(__float_as_uint(a0)), "r"(__float_as_uint(a1)),
          "r"(__float_as_uint(a2)), "r"(__float_as_uint(a3)),
          "r"(__float_as_uint(b0)), "r"(__float_as_uint(b1)));
}

__device__ __forceinline__ void cp16(uint32_t dst_smem, const float* src) {
    asm volatile("cp.async.cg.shared.global [%0], [%1], 16;\n"
                 :: "r"(dst_smem), "l"(src));
}
__device__ __forceinline__ void cp_commit() {
    asm volatile("cp.async.commit_group;\n" ::: "memory");
}
template <int N_>
__device__ __forceinline__ void cp_wait() {
    asm volatile("cp.async.wait_group %0;\n" :: "n"(N_) : "memory");
}

// fast e^x for x <= 0 on the FMA pipe (411M MUFU EX2 would cost ~2.9 ms).
__device__ __forceinline__ float fexp(float x) {
    float y = fmaxf(x * 1.4426950408889634f, -126.0f);
    float r = rintf(y);
    float f = y - r;
    float p = 1.3333558146428443e-3f;
    p = fmaf(p, f, 9.618129107628477e-3f);
    p = fmaf(p, f, 5.550410866482158e-2f);
    p = fmaf(p, f, 2.402265069591007e-1f);
    p = fmaf(p, f, 6.931471805599453e-1f);
    p = fmaf(p, f, 1.0f);
    return p * __int_as_float(((int)r + 127) << 23);
}

// ---------------------------------------------------------------------------
// pre-convert: tf32-round once AND permute k within each 8-group so the mma
// fragment pair (k, k+4) is contiguous: logical l -> phys (l&3)*2 + (l>>2).
// 8 consecutive logical floats (lo,hi) -> phys {lo.x,hi.x,lo.y,hi.y,
//                                               lo.z,hi.z,lo.w,hi.w}
// ---------------------------------------------------------------------------

__device__ __forceinline__ void perm_store(float4* dst, int i8, float4 lo, float4 hi) {
    dst[2 * i8]     = make_float4(to_tf32(lo.x), to_tf32(hi.x), to_tf32(lo.y), to_tf32(hi.y));
    dst[2 * i8 + 1] = make_float4(to_tf32(lo.z), to_tf32(hi.z), to_tf32(lo.w), to_tf32(hi.w));
}

__global__ __launch_bounds__(256)
void cvt_A_kernel(const float4* __restrict__ A) {
    const int n8 = M_DIM * K_DIM / 8;
    float4* dst = reinterpret_cast<float4*>(g_Ac);
    int stride = gridDim.x * blockDim.x;
    for (int i = blockIdx.x * blockDim.x + threadIdx.x; i < n8; i += stride)
        perm_store(dst, i, A[2 * i], A[2 * i + 1]);
}

__global__ __launch_bounds__(256)
void cvt_W_kernel(const float4* __restrict__ W) {
    const int n8_real  = N_DIM * (K_DIM / 8);
    const int n8_total = NPAD  * (K_DIM / 8);
    float4* dst = reinterpret_cast<float4*>(g_Wc);
    int stride = gridDim.x * blockDim.x;
    float4 z = make_float4(0.f, 0.f, 0.f, 0.f);
    for (int i = blockIdx.x * blockDim.x + threadIdx.x; i < n8_total; i += stride) {
        if (i < n8_real) perm_store(dst, i, W[2 * i], W[2 * i + 1]);
        else { dst[2 * i] = z; dst[2 * i + 1] = z; }
    }
}

// ---------------------------------------------------------------------------
// GEMM: C[m,n] = sum_k Ac[m,k] * Wc[n,k].  128x128x32 tile, 8 warps (2x4),
// warp tile 64x32, m16n8k8 tf32, float2 fragment loads, cp.async 2-stage,
// 2 CTAs/SM. Epilogue also emits per-tile row max into g_tmax.
// ---------------------------------------------------------------------------

__device__ __forceinline__ void issue_tile(uint32_t sA, uint32_t sB,
                                           const float* __restrict__ Abase,
                                           const float* __restrict__ Bbase,
                                           int kk, int tid) {
#pragma unroll
    for (int i = 0; i < 4; i++) {
        int id = tid + i * 256;
        int r = id >> 3, c4 = id & 7;
        uint32_t so = (uint32_t)(r * AS_STRIDE + c4 * 4) * 4u;
        cp16(sA + so, Abase + (size_t)r * K_DIM + kk + c4 * 4);
        cp16(sB + so, Bbase + (size_t)r * K_DIM + kk + c4 * 4);
    }
}

__global__ __launch_bounds__(256, 2)
void gemm_tf32_kernel(float* __restrict__ C) {
    extern __shared__ float smem[];
    const uint32_t sbase = (uint32_t)__cvta_generic_to_shared(smem);
    const uint32_t sA0 = sbase;
    const uint32_t sB0 = sbase + 2u * TILE_FLOATS * 4u;
    const uint32_t bufstride = TILE_FLOATS * 4u;

    const int tid = threadIdx.x;

    // panel rasterization: bid -> (x, y); y fastest so a wave shares A in L2
    const int bid = blockIdx.x;
    const int panel = bid / (64 * PW);
    const int rem = bid % (64 * PW);
    const int y = rem & 63;
    const int x = panel * PW + (rem >> 6);
    if (x >= NX_VALID) return;      // pad tiles produce no output

    const int m0 = y * BM;
    const int n0 = x * BN;

    const float* Abase = g_Ac + (size_t)m0 * K_DIM;
    const float* Bbase = g_Wc + (size_t)n0 * K_DIM;

    const int lane = tid & 31;
    const int g = lane >> 2;     // 0..7
    const int tg = lane & 3;     // 0..3
    const int wid = tid >> 5;
    const int wm = (wid >> 2) * 64;
    const int wn = (wid & 3) * 32;

    float acc[4][4][4];
#pragma unroll
    for (int mt = 0; mt < 4; mt++)
#pragma unroll
        for (int nt = 0; nt < 4; nt++)
#pragma unroll
            for (int i = 0; i < 4; i++) acc[mt][nt][i] = 0.f;

    const int tiles = K_DIM / BK;   // 32

    issue_tile(sA0, sB0, Abase, Bbase, 0, tid);
    cp_commit();
    issue_tile(sA0 + bufstride, sB0 + bufstride, Abase, Bbase, BK, tid);
    cp_commit();
    cp_wait<1>();
    __syncthreads();

    for (int t = 0; t < tiles; t++) {
        const int b = t & 1;
        const float* Ac = smem + b * TILE_FLOATS;
        const float* Bc = smem + (2 + b) * TILE_FLOATS;

#pragma unroll
        for (int ks = 0; ks < 4; ks++) {
            const int kc = ks * 8 + 2 * tg;   // permuted column of the k-pair
            float2 a0[4], a1[4], bf[4];
#pragma unroll
            for (int mt = 0; mt < 4; mt++) {
                const float2* pa = reinterpret_cast<const float2*>(
                    Ac + (wm + mt * 16 + g) * AS_STRIDE + kc);
                a0[mt] = pa[0];                         // row g      : (k, k+4)
                a1[mt] = pa[8 * AS_STRIDE / 2];         // row g+8    : (k, k+4)
            }
#pragma unroll
            for (int nt = 0; nt < 4; nt++)
                bf[nt] = *reinterpret_cast<const float2*>(
                    Bc + (wn + nt * 8 + g) * AS_STRIDE + kc);
#pragma unroll
            for (int mt = 0; mt < 4; mt++)
#pragma unroll
                for (int nt = 0; nt < 4; nt++)
                    mma_tf32(acc[mt][nt], a0[mt].x, a1[mt].x, a0[mt].y, a1[mt].y,
                             bf[nt].x, bf[nt].y);
        }

        if (t + 2 < tiles) {
            __syncthreads();
            issue_tile(sA0 + b * bufstride, sB0 + b * bufstride,
                       Abase, Bbase, (t + 2) * BK, tid);
            cp_commit();
            cp_wait<1>();
            __syncthreads();
        } else if (t + 1 < tiles) {
            cp_wait<0>();
            __syncthreads();
        }
    }

    // ---- store C (N odd -> scalar stores; guard pad columns) ----
#pragma unroll
    for (int mt = 0; mt < 4; mt++) {
        int r = m0 + wm + mt * 16 + g;
        size_t b0 = (size_t)r * N_DIM;
        size_t b1 = (size_t)(r + 8) * N_DIM;
#pragma unroll
        for (int nt = 0; nt < 4; nt++) {
            int c = n0 + wn + nt * 8 + 2 * tg;
            const float* d = acc[mt][nt];
            if (c < N_DIM)     { C[b0 + c] = d[0];     C[b1 + c] = d[2]; }
            if (c + 1 < N_DIM) { C[b0 + c + 1] = d[1]; C[b1 + c + 1] = d[3]; }
        }
    }

    // ---- per-tile row max -> g_tmax (fuses LSE pass 1 into the GEMM) ----
    __syncthreads();                 // done with smem tiles; reuse as reduce buf
    float* red = smem;               // [128 rows][4 col-slabs]
#pragma unroll
    for (int mt = 0; mt < 4; mt++) {
#pragma unroll
        for (int h = 0; h < 2; h++) {    // h=0: row g, h=1: row g+8
            float v = -FLT_MAX;
#pragma unroll
            for (int nt = 0; nt < 4; nt++) {
                int c = n0 + wn + nt * 8 + 2 * tg;
                const float* d = acc[mt][nt];
                if (c < N_DIM)     v = fmaxf(v, d[h ? 2 : 0]);
                if (c + 1 < N_DIM) v = fmaxf(v, d[h ? 3 : 1]);
            }
            v = fmaxf(v, __shfl_xor_sync(0xffffffffu, v, 1));
            v = fmaxf(v, __shfl_xor_sync(0xffffffffu, v, 2));
            if (tg == 0)
                red[(wm + mt * 16 + g + h * 8) * 4 + (wid & 3)] = v;
        }
    }
    __syncthreads();
    if (tid < 128) {
        float v = fmaxf(fmaxf(red[tid * 4 + 0], red[tid * 4 + 1]),
                        fmaxf(red[tid * 4 + 2], red[tid * 4 + 3]));
        g_tmax[(size_t)(m0 + tid) * NX_TILES + x] = v;
    }
}

// ---------------------------------------------------------------------------
// Per-row NLL: row max comes precomputed from g_tmax (tiny read), so the
// 1.65 GB logits array is streamed exactly ONCE for the sum-exp.
// ---------------------------------------------------------------------------

__global__ __launch_bounds__(256)
void lse_nll_kernel(const float* __restrict__ logits,
                    const int* __restrict__ targets) {
    __shared__ float red[8];
    __shared__ float row_max_sh;
    const int row = blockIdx.x;
    const int tid = threadIdx.x;
    const float* x = logits + (size_t)row * N_DIM;
    const float* tm = g_tmax + (size_t)row * NX_TILES;

    float mx = -FLT_MAX;
    for (int j = tid; j < NX_VALID; j += 256) mx = fmaxf(mx, tm[j]);
#pragma unroll
    for (int o = 16; o; o >>= 1) mx = fmaxf(mx, __shfl_xor_sync(0xffffffffu, mx, o));
    if ((tid & 31) == 0) red[tid >> 5] = mx;
    __syncthreads();
    if (tid < 32) {
        float v = (tid < 8) ? red[tid] : -FLT_MAX;
#pragma unroll
        for (int o = 4; o; o >>= 1) v = fmaxf(v, __shfl_xor_sync(0xffffffffu, v, o));
        if (tid == 0) row_max_sh = v;
    }
    __syncthreads();
    const float rmax = row_max_sh;

    float s = 0.f;
    for (int j = tid; j < N_DIM; j += 256) s += fexp(x[j] - rmax);
#pragma unroll
    for (int o = 16; o; o >>= 1) s += __shfl_xor_sync(0xffffffffu, s, o);
    if ((tid & 31) == 0) red[tid >> 5] = s;
    __syncthreads();
    if (tid == 0) {
        float tot = 0.f;
#pragma unroll
        for (int w = 0; w < 8; w++) tot += red[w];
        int t = targets[row];
        t = (t < 0) ? 0 : (t >= N_DIM ? N_DIM - 1 : t);
        g_row_nll[row] = rmax + logf(tot) - x[t];
    }
}

__global__ __launch_bounds__(256)
void mean_nll_kernel(float* __restrict__ loss_out, int M) {
    __shared__ float red[8];
    float s = 0.f;
    for (int j = threadIdx.x; j < M; j += 256) s += g_row_nll[j];
#pragma unroll
    for (int o = 16; o; o >>= 1) s += __shfl_xor_sync(0xffffffffu, s, o);
    if ((threadIdx.x & 31) == 0) red[threadIdx.x >> 5] = s;
    __syncthreads();
    if (threadIdx.x == 0) {
        float t = 0.f;
#pragma unroll
        for (int w = 0; w < 8; w++) t += red[w];
        loss_out[0] = t / (float)M;
    }
}

// ---------------------------------------------------------------------------
// launch — bind inputs BY ELEMENT COUNT (robust to metadata ordering)
// ---------------------------------------------------------------------------

extern "C" void kernel_launch(void* const* d_in, const int* in_sizes, int n_in,
                              void* d_out, int out_size) {
    int it = 0, ia = 0, iw = 0;
    for (int i = 1; i < n_in; i++) {
        if (in_sizes[i] < in_sizes[it]) it = i;
        if (in_sizes[i] > in_sizes[iw]) iw = i;
    }
    for (int i = 0; i < n_in; i++)
        if (i != it && i != iw) ia = i;

    const int* tgt = (const int*)d_in[it];     // targets [M] (int64 lowered to int32)
    const float* A = (const float*)d_in[ia];   // inputs  [M, K] fp32
    const float* W = (const float*)d_in[iw];   // W       [N, K] fp32
    float* out = (float*)d_out;

    const int M = in_sizes[ia] / K_DIM;   // 8192

    cudaFuncSetAttribute((const void*)gemm_tf32_kernel,
                         cudaFuncAttributeMaxDynamicSharedMemorySize, SMEM_BYTES);

    cvt_A_kernel<<<2048, 256>>>(reinterpret_cast<const float4*>(A));
    cvt_W_kernel<<<8192, 256>>>(reinterpret_cast<const float4*>(W));

    gemm_tf32_kernel<<<NX_TILES * 64, 256, SMEM_BYTES>>>(out);

    lse_nll_kernel<<<M, 256>>>(out, tgt);
    mean_nll_kernel<<<1, 256>>>(out + (size_t)out_size - 1, M);
}